// round 16
// baseline (speedup 1.0000x reference)
#include <cuda_runtime.h>
#include <float.h>

#define BB 32
#define NN 4096
#define DD 768
#define CC 10
#define KSEL 16

// scratch scores [B, N] — __device__ global (no allocations allowed)
__device__ float g_scores[BB * NN];

// Kernel 1: s[b,n] = H[b,n,:] . w_score + b_score
// One warp per row; each lane handles 6 float4 (24 floats) of the 768-dim row.
__global__ __launch_bounds__(256) void score_kernel(
    const float* __restrict__ H,
    const float* __restrict__ w,
    const float* __restrict__ b_score)
{
    __shared__ float4 wsh[DD / 4];  // 192 float4
    int tid = threadIdx.x;
    for (int i = tid; i < DD / 4; i += blockDim.x)
        wsh[i] = reinterpret_cast<const float4*>(w)[i];
    __syncthreads();

    int warp = tid >> 5;
    int lane = tid & 31;
    int row  = blockIdx.x * 8 + warp;  // 131072 rows total

    const float4* h = reinterpret_cast<const float4*>(H + (size_t)row * DD);

    float4 a[6];
#pragma unroll
    for (int i = 0; i < 6; i++)
        a[i] = h[lane + i * 32];

    float acc = 0.0f;
#pragma unroll
    for (int i = 0; i < 6; i++) {
        float4 wv = wsh[lane + i * 32];
        acc += a[i].x * wv.x + a[i].y * wv.y + a[i].z * wv.z + a[i].w * wv.w;
    }
#pragma unroll
    for (int off = 16; off; off >>= 1)
        acc += __shfl_down_sync(0xffffffffu, acc, off);

    if (lane == 0)
        g_scores[row] = acc + b_score[0];
}

// combine two (value, index) candidates; lowest index wins ties
__device__ __forceinline__ void cand_take(float& bv, int& bi, float ov, int oi) {
    if (ov > bv || (ov == bv && oi < bi)) { bv = ov; bi = oi; }
}

// butterfly allreduce: all lanes converge to the warp's best (value, index)
__device__ __forceinline__ void warp_arg_allreduce(float& v, int& i) {
#pragma unroll
    for (int off = 16; off; off >>= 1) {
        float ov = __shfl_xor_sync(0xffffffffu, v, off);
        int   oi = __shfl_xor_sync(0xffffffffu, i, off);
        cand_take(v, i, ov, oi);
    }
}

// Kernel 2: per-batch top-16 via two-phase warp-local selection (2 barriers
// total), A scatter, mean-pool, classifier GEMV. One block per batch.
__global__ __launch_bounds__(256) void topk_kernel(
    const float* __restrict__ H,
    const float* __restrict__ W_cls,
    const float* __restrict__ b_cls,
    float* __restrict__ out)
{
    int b    = blockIdx.x;
    int tid  = threadIdx.x;
    int lane = tid & 31;
    int warp = tid >> 5;

    __shared__ float cand_v[8 * KSEL];   // per-warp top-16 values
    __shared__ int   cand_i[8 * KSEL];   // per-warp top-16 indices
    __shared__ int   topk_sh[KSEL];
    __shared__ float M[DD];
    __shared__ float wred[8 * CC];

    float*       A  = out + BB * CC + (size_t)b * NN;
    const float* sg = g_scores + b * NN;

    // each thread owns global indices i = j*256 + tid, j = 0..15, in registers
    float sl[16];
#pragma unroll
    for (int j = 0; j < 16; j++)
        sl[j] = sg[j * 256 + tid];

    // zero A slice (coalesced, overlaps with selection latency)
    float4 zero4 = make_float4(0.f, 0.f, 0.f, 0.f);
#pragma unroll
    for (int j = 0; j < 4; j++)
        reinterpret_cast<float4*>(A)[j * 256 + tid] = zero4;

    // lane-local candidate (strict > keeps lowest j => lowest global index)
    float cv = sl[0]; int cj = 0;
#pragma unroll
    for (int j = 1; j < 16; j++)
        if (sl[j] > cv) { cv = sl[j]; cj = j; }
    int ci = cj * 256 + tid;

    // ---- Phase 1: each warp selects ITS top-16 of its 512 elements.
    // No block barriers; butterfly allreduce keeps all lanes in agreement.
    for (int k = 0; k < KSEL; k++) {
        float v = cv; int i = ci;
        warp_arg_allreduce(v, i);
        if (lane == 0) {
            cand_v[warp * KSEL + k] = v;
            cand_i[warp * KSEL + k] = i;
        }
        if ((i & 255) == tid) {              // owner invalidates + recomputes
            sl[i >> 8] = -FLT_MAX;
            float nv = sl[0]; int nj = 0;
#pragma unroll
            for (int j = 1; j < 16; j++)
                if (sl[j] > nv) { nv = sl[j]; nj = j; }
            cv = nv; ci = nj * 256 + tid;
        }
    }
    __syncthreads();                          // (1) all candidate lists ready

    // ---- Phase 2: warp 0 merges 128 candidates -> global top-16.
    // 4 candidates per lane in registers; zero barriers.
    if (warp == 0) {
        float mv[4]; int mi[4];
#pragma unroll
        for (int r = 0; r < 4; r++) {
            mv[r] = cand_v[lane + 32 * r];
            mi[r] = cand_i[lane + 32 * r];
        }
        for (int k = 0; k < KSEL; k++) {
            float v = mv[0]; int i = mi[0];
#pragma unroll
            for (int r = 1; r < 4; r++)
                cand_take(v, i, mv[r], mi[r]);
            warp_arg_allreduce(v, i);
            if (lane == 0) topk_sh[k] = i;
            // invalidate the winner wherever it lives (indices are unique)
#pragma unroll
            for (int r = 0; r < 4; r++)
                if (mi[r] == i) mv[r] = -FLT_MAX;
        }
    }
    __syncthreads();                          // (2) topk_sh visible to all

    // scatter A: 1/16 at each selected index
    if (tid < KSEL)
        A[topk_sh[tid]] = 1.0f / (float)KSEL;

    // M = mean of 16 selected rows; thread owns dims tid, tid+256, tid+512
    {
        float a0 = 0.f, a1 = 0.f, a2 = 0.f;
#pragma unroll
        for (int k = 0; k < KSEL; k++) {
            const float* row = H + ((size_t)b * NN + topk_sh[k]) * DD;
            a0 += row[tid];
            a1 += row[tid + 256];
            a2 += row[tid + 512];
        }
        M[tid]       = a0 * (1.0f / (float)KSEL);
        M[tid + 256] = a1 * (1.0f / (float)KSEL);
        M[tid + 512] = a2 * (1.0f / (float)KSEL);
    }
    __syncthreads();

    // logits = M @ W_cls + b_cls (deterministic: warp shuffle tree + serial 8)
    float part[CC];
#pragma unroll
    for (int c = 0; c < CC; c++) part[c] = 0.0f;
    for (int d = tid; d < DD; d += 256) {
        float m = M[d];
#pragma unroll
        for (int c = 0; c < CC; c++)
            part[c] += m * W_cls[d * CC + c];
    }
#pragma unroll
    for (int c = 0; c < CC; c++) {
        float v = part[c];
#pragma unroll
        for (int off = 16; off; off >>= 1)
            v += __shfl_down_sync(0xffffffffu, v, off);
        if (lane == 0) wred[warp * CC + c] = v;
    }
    __syncthreads();

    if (tid < CC) {
        float acc = b_cls[tid];
#pragma unroll
        for (int wq = 0; wq < 8; wq++)
            acc += wred[wq * CC + tid];
        out[b * CC + tid] = acc;
    }
}

extern "C" void kernel_launch(void* const* d_in, const int* in_sizes, int n_in,
                              void* d_out, int out_size)
{
    const float* H   = (const float*)d_in[0];
    const float* w   = (const float*)d_in[1];
    const float* bs  = (const float*)d_in[2];
    const float* Wc  = (const float*)d_in[3];
    const float* bc  = (const float*)d_in[4];
    float*       out = (float*)d_out;

    score_kernel<<<(BB * NN) / 8, 256>>>(H, w, bs);
    topk_kernel<<<BB, 256>>>(H, Wc, bc, out);
}